// round 11
// baseline (speedup 1.0000x reference)
#include <cuda_runtime.h>

#define NN 100000
#define NE 1000000
#define DI 128
#define DO 64
#define SB 1024
#define NBLK_SCAN ((NN + SB - 1) / SB)   // 98
#define NBP2 ((NN * 16 + 255) / 256)     // 6250 pass2 blocks (exact: 16 nodes/blk)
#define FULLM 0xffffffffu

// ---------------- scratch (device globals) ----------------------------------
__device__ float g_h0[NN * DO];
__device__ float g_h [NN * DO];
__device__ float g_A [NN * DO];
__device__ int   g_degd[NN];
__device__ int   g_degs[NN];
__device__ int   g_offd[NN + 1];
__device__ int   g_offs[NN + 1];
__device__ int   g_curd[NN];
__device__ int   g_curs[NN];
__device__ int   g_csrd[NE];
__device__ int   g_csrs[NE];
__device__ int   g_bsumd[NBLK_SCAN + 1];
__device__ int   g_bsums[NBLK_SCAN + 1];
__device__ float g_e[NN];
__device__ float g_nh[NN];
__device__ float g_q[NN];
__device__ float g_dinv[NN];
__device__ float g_pm[NBP2];
__device__ float g_pz[NBP2];
__device__ float g_pt[NBP2];

// ---------------- CSR build --------------------------------------------------
__global__ __launch_bounds__(256) void k_zero() {
    int i = blockIdx.x * 256 + threadIdx.x;
    if (i < NN) { g_degd[i] = 0; g_degs[i] = 0; }
}

// 4 edges per thread
__global__ __launch_bounds__(256) void k_deg(const int* __restrict__ ei) {
    int e = (blockIdx.x * 256 + threadIdx.x) * 4;
    if (e + 3 < NE) {
        int4 s = *(const int4*)(ei + e);
        int4 d = *(const int4*)(ei + NE + e);
        atomicAdd(&g_degs[s.x], 1); atomicAdd(&g_degs[s.y], 1);
        atomicAdd(&g_degs[s.z], 1); atomicAdd(&g_degs[s.w], 1);
        atomicAdd(&g_degd[d.x], 1); atomicAdd(&g_degd[d.y], 1);
        atomicAdd(&g_degd[d.z], 1); atomicAdd(&g_degd[d.w], 1);
    } else {
        for (; e < NE; e++) {
            atomicAdd(&g_degs[ei[e]], 1);
            atomicAdd(&g_degd[ei[NE + e]], 1);
        }
    }
}

__global__ __launch_bounds__(SB) void k_scan1() {
    __shared__ int sd[SB], ss[SB];
    int t = threadIdx.x;
    int i = blockIdx.x * SB + t;
    int a = (i < NN) ? g_degd[i] : 0;
    int b = (i < NN) ? g_degs[i] : 0;
    sd[t] = a; ss[t] = b;
    __syncthreads();
    for (int o = 1; o < SB; o <<= 1) {
        int va = (t >= o) ? sd[t - o] : 0;
        int vb = (t >= o) ? ss[t - o] : 0;
        __syncthreads();
        sd[t] += va; ss[t] += vb;
        __syncthreads();
    }
    if (i < NN) { g_offd[i] = sd[t] - a; g_offs[i] = ss[t] - b; }
    if (t == SB - 1) { g_bsumd[blockIdx.x] = sd[t]; g_bsums[blockIdx.x] = ss[t]; }
}

// scan2 fused into scan3
__global__ __launch_bounds__(256) void k_scan3() {
    __shared__ int pd[128], ps[128];
    int t = threadIdx.x;
    if (t < 128) {
        pd[t] = (t < NBLK_SCAN) ? g_bsumd[t] : 0;
        ps[t] = (t < NBLK_SCAN) ? g_bsums[t] : 0;
    }
    __syncthreads();
    for (int o = 1; o < 128; o <<= 1) {
        int va = 0, vb = 0;
        if (t < 128 && t >= o) { va = pd[t - o]; vb = ps[t - o]; }
        __syncthreads();
        if (t < 128) { pd[t] += va; ps[t] += vb; }
        __syncthreads();
    }
    int i = blockIdx.x * 256 + t;
    if (i < NN) {
        int blk = i / SB;
        int exd = (blk == 0) ? 0 : pd[blk - 1];
        int exs = (blk == 0) ? 0 : ps[blk - 1];
        int od = g_offd[i] + exd;
        int os = g_offs[i] + exs;
        g_offd[i] = od; g_curd[i] = od;
        g_offs[i] = os; g_curs[i] = os;
        g_dinv[i] = rsqrtf((float)(g_degd[i] + 1));
    }
    if (i == 0) { g_offd[NN] = NE; g_offs[NN] = NE; }
}

__global__ __launch_bounds__(256) void k_fill_d(const int* __restrict__ ei) {
    int e = blockIdx.x * 256 + threadIdx.x;
    if (e >= NE) return;
    int s = ei[e], d = ei[NE + e];
    int pd = atomicAdd(&g_curd[d], 1);
    g_csrd[pd] = s;
}

__global__ __launch_bounds__(256) void k_fill_s(const int* __restrict__ ei) {
    int e = blockIdx.x * 256 + threadIdx.x;
    if (e >= NE) return;
    int s = ei[e], d = ei[NE + e];
    int ps = atomicAdd(&g_curs[s], 1);
    g_csrs[ps] = d;
}

// ---------------- GEMM: h0 = x @ W (128 rows/block, 8x8 per thread) ----------
__global__ __launch_bounds__(128) void k_gemm(const float* __restrict__ x,
                                              const float* __restrict__ W) {
    __shared__ float Ws[DI * DO];
    __shared__ float xs[16 * 128];
    int t = threadIdx.x;
    int row0 = blockIdx.x * 128;
    for (int i = t * 4; i < DI * DO; i += 128 * 4)
        *(float4*)(Ws + i) = *(const float4*)(W + i);

    int cg = t & 7, rt = t >> 3;
    float acc[8][8];
#pragma unroll
    for (int i = 0; i < 8; i++)
#pragma unroll
        for (int j = 0; j < 8; j++) acc[i][j] = 0.f;

    int grow = row0 + t;
    bool rok = grow < NN;

    for (int kc = 0; kc < 8; kc++) {
        __syncthreads();
        float4 xa = rok ? *(const float4*)(x + grow * DI + kc * 16 + 0)  : make_float4(0,0,0,0);
        float4 xb = rok ? *(const float4*)(x + grow * DI + kc * 16 + 4)  : make_float4(0,0,0,0);
        float4 xc = rok ? *(const float4*)(x + grow * DI + kc * 16 + 8)  : make_float4(0,0,0,0);
        float4 xd = rok ? *(const float4*)(x + grow * DI + kc * 16 + 12) : make_float4(0,0,0,0);
        xs[0*128+t]=xa.x;  xs[1*128+t]=xa.y;  xs[2*128+t]=xa.z;  xs[3*128+t]=xa.w;
        xs[4*128+t]=xb.x;  xs[5*128+t]=xb.y;  xs[6*128+t]=xb.z;  xs[7*128+t]=xb.w;
        xs[8*128+t]=xc.x;  xs[9*128+t]=xc.y;  xs[10*128+t]=xc.z; xs[11*128+t]=xc.w;
        xs[12*128+t]=xd.x; xs[13*128+t]=xd.y; xs[14*128+t]=xd.z; xs[15*128+t]=xd.w;
        __syncthreads();
#pragma unroll
        for (int k = 0; k < 16; k++) {
            float4 x0 = *(const float4*)(xs + k * 128 + rt * 8);
            float4 x1 = *(const float4*)(xs + k * 128 + rt * 8 + 4);
            float4 w0 = *(const float4*)(Ws + (kc * 16 + k) * DO + cg * 8);
            float4 w1 = *(const float4*)(Ws + (kc * 16 + k) * DO + cg * 8 + 4);
            float xv[8] = {x0.x, x0.y, x0.z, x0.w, x1.x, x1.y, x1.z, x1.w};
            float wv[8] = {w0.x, w0.y, w0.z, w0.w, w1.x, w1.y, w1.z, w1.w};
#pragma unroll
            for (int i = 0; i < 8; i++)
#pragma unroll
                for (int j = 0; j < 8; j++)
                    acc[i][j] += xv[i] * wv[j];
        }
    }
#pragma unroll
    for (int i = 0; i < 8; i++) {
        int gr = row0 + rt * 8 + i;
        if (gr < NN) {
            float4* p = (float4*)(g_h0 + gr * DO + cg * 8);
            p[0] = make_float4(acc[i][0], acc[i][1], acc[i][2], acc[i][3]);
            p[1] = make_float4(acc[i][4], acc[i][5], acc[i][6], acc[i][7]);
        }
    }
}

// ---------------- online triple helper ----------------------------------------
__device__ __forceinline__ void triple_merge(float& m, float& z, float& t,
                                             float m2, float z2, float t2) {
    float M = fmaxf(m, m2);
    float a = expf(m - M), c = expf(m2 - M);
    z = z * a + z2 * c;
    t = t * a + t2 * c;
    m = M;
}

// ---------------- gather passes (16 lanes/node, 4-edge unroll) ----------------
__global__ __launch_bounds__(256) void k_pass1(const float* __restrict__ b) {
    int t = blockIdx.x * 256 + threadIdx.x;
    int v = t >> 4, q = t & 15;
    if (v >= NN) return;
    int start = g_offd[v], end = g_offd[v + 1];
    float ax0 = 0.f, ay0 = 0.f, az0 = 0.f, aw0 = 0.f;
    float ax1 = 0.f, ay1 = 0.f, az1 = 0.f, aw1 = 0.f;
    int i = start;
    for (; i + 3 < end; i += 4) {
        int i0 = g_csrd[i], i1 = g_csrd[i + 1], i2 = g_csrd[i + 2], i3 = g_csrd[i + 3];
        float d0 = g_dinv[i0], d1 = g_dinv[i1], d2 = g_dinv[i2], d3 = g_dinv[i3];
        float4 u0 = *(const float4*)(g_h0 + i0 * DO + q * 4);
        float4 u1 = *(const float4*)(g_h0 + i1 * DO + q * 4);
        float4 u2 = *(const float4*)(g_h0 + i2 * DO + q * 4);
        float4 u3 = *(const float4*)(g_h0 + i3 * DO + q * 4);
        ax0 += u0.x * d0 + u2.x * d2; ay0 += u0.y * d0 + u2.y * d2;
        az0 += u0.z * d0 + u2.z * d2; aw0 += u0.w * d0 + u2.w * d2;
        ax1 += u1.x * d1 + u3.x * d3; ay1 += u1.y * d1 + u3.y * d3;
        az1 += u1.z * d1 + u3.z * d3; aw1 += u1.w * d1 + u3.w * d3;
    }
    for (; i < end; i++) {
        int i0 = g_csrd[i];
        float d0 = g_dinv[i0];
        float4 u0 = *(const float4*)(g_h0 + i0 * DO + q * 4);
        ax0 += u0.x * d0; ay0 += u0.y * d0; az0 += u0.z * d0; aw0 += u0.w * d0;
    }
    float ax = ax0 + ax1, ay = ay0 + ay1, az = az0 + az1, aw = aw0 + aw1;
    float dv = g_dinv[v];
    float dv2 = dv * dv;
    float4 h0v = *(const float4*)(g_h0 + v * DO + q * 4);
    float4 bv  = *(const float4*)(b + q * 4);
    float4 h;
    h.x = dv * ax + dv2 * h0v.x + bv.x;
    h.y = dv * ay + dv2 * h0v.y + bv.y;
    h.z = dv * az + dv2 * h0v.z + bv.z;
    h.w = dv * aw + dv2 * h0v.w + bv.w;
    *(float4*)(g_h + v * DO + q * 4) = h;
    float p = h.x * h.x + h.y * h.y + h.z * h.z + h.w * h.w;
#pragma unroll
    for (int off = 8; off; off >>= 1)
        p += __shfl_down_sync(FULLM, p, off, 16);
    if (q == 0) g_nh[v] = p;
}

// pass2 + per-block softmax triple (exactly 16 nodes per block)
__global__ __launch_bounds__(256) void k_pass2(const float* __restrict__ temp) {
    __shared__ float se[16];
    int t = blockIdx.x * 256 + threadIdx.x;
    int v = t >> 4, q = t & 15;
    int start = g_offd[v], end = g_offd[v + 1];
    float ax0 = 0.f, ay0 = 0.f, az0 = 0.f, aw0 = 0.f;
    float ax1 = 0.f, ay1 = 0.f, az1 = 0.f, aw1 = 0.f;
    float es = 0.f;
    int i = start;
    for (; i + 3 < end; i += 4) {
        int i0 = g_csrd[i], i1 = g_csrd[i + 1], i2 = g_csrd[i + 2], i3 = g_csrd[i + 3];
        float4 u0 = *(const float4*)(g_h + i0 * DO + q * 4);
        float4 u1 = *(const float4*)(g_h + i1 * DO + q * 4);
        float4 u2 = *(const float4*)(g_h + i2 * DO + q * 4);
        float4 u3 = *(const float4*)(g_h + i3 * DO + q * 4);
        ax0 += u0.x + u2.x; ay0 += u0.y + u2.y; az0 += u0.z + u2.z; aw0 += u0.w + u2.w;
        ax1 += u1.x + u3.x; ay1 += u1.y + u3.y; az1 += u1.z + u3.z; aw1 += u1.w + u3.w;
        if (q == 0) es += g_nh[i0] + g_nh[i1] + g_nh[i2] + g_nh[i3];
    }
    for (; i < end; i++) {
        int i0 = g_csrd[i];
        float4 u0 = *(const float4*)(g_h + i0 * DO + q * 4);
        ax0 += u0.x; ay0 += u0.y; az0 += u0.z; aw0 += u0.w;
        if (q == 0) es += g_nh[i0];
    }
    float ax = ax0 + ax1, ay = ay0 + ay1, az = az0 + az1, aw = aw0 + aw1;
    *(float4*)(g_A + v * DO + q * 4) = make_float4(ax, ay, az, aw);
    float4 hv = *(const float4*)(g_h + v * DO + q * 4);
    float p = hv.x * ax + hv.y * ay + hv.z * az + hv.w * aw;
#pragma unroll
    for (int off = 8; off; off >>= 1)
        p += __shfl_down_sync(FULLM, p, off, 16);
    float e = 0.f;
    if (q == 0) {
        e = (float)g_degd[v] * g_nh[v] - 2.f * p + es;
        g_e[v] = e;
        se[threadIdx.x >> 4] = e;
    }
    __syncthreads();
    // threads 0..15 hold the 16 node-e's; warp-reduce an online triple
    if (threadIdx.x < 16) {
        float tmp = temp[0];
        float m = -se[threadIdx.x] / tmp;
        float z = 1.f, tt = m;
        tt = m;  // t = s*exp(0) = s
#pragma unroll
        for (int off = 8; off; off >>= 1) {
            float m2 = __shfl_down_sync(0x0000ffffu, m, off, 16);
            float z2 = __shfl_down_sync(0x0000ffffu, z, off, 16);
            float t2 = __shfl_down_sync(0x0000ffffu, tt, off, 16);
            triple_merge(m, z, tt, m2, z2, t2);
        }
        if (threadIdx.x == 0) {
            g_pm[blockIdx.x] = m; g_pz[blockIdx.x] = z; g_pt[blockIdx.x] = tt;
        }
    }
}

// merge all block triples, compute q
__global__ __launch_bounds__(256) void k_q(const float* __restrict__ temp) {
    __shared__ float sm[256], sz[256], st[256];
    int tx = threadIdx.x;
    float m = -1e30f, z = 0.f, t = 0.f;
    for (int j = tx; j < NBP2; j += 256)
        triple_merge(m, z, t, g_pm[j], g_pz[j], g_pt[j]);
    sm[tx] = m; sz[tx] = z; st[tx] = t;
    __syncthreads();
    for (int o = 128; o; o >>= 1) {
        if (tx < o) {
            float mm = sm[tx], zz = sz[tx], tt = st[tx];
            triple_merge(mm, zz, tt, sm[tx + o], sz[tx + o], st[tx + o]);
            sm[tx] = mm; sz[tx] = zz; st[tx] = tt;
        }
        __syncthreads();
    }
    float M = sm[0], Z = sz[0], T = st[0];
    float invZ = 1.f / Z;
    float L = M + logf(Z);
    float H = L - T * invZ;
    int v = blockIdx.x * 256 + tx;
    if (v >= NN) return;
    float tmp = temp[0];
    float s = -g_e[v] / tmp;
    g_q[v] = expf(s - M) * invZ * (s - L + H);
}

// pass3 + final (16 lanes/node, 4-edge unroll)
__global__ __launch_bounds__(256) void k_pass3(const float* __restrict__ wgt,
                                               float* __restrict__ out) {
    int t = blockIdx.x * 256 + threadIdx.x;
    int v = t >> 4, q = t & 15;
    if (v >= NN) return;
    int start = g_offs[v], end = g_offs[v + 1];
    float bx0 = 0.f, by0 = 0.f, bz0 = 0.f, bw0 = 0.f;
    float bx1 = 0.f, by1 = 0.f, bz1 = 0.f, bw1 = 0.f;
    float Qs = 0.f;
    int i = start;
    for (; i + 3 < end; i += 4) {
        int i0 = g_csrs[i], i1 = g_csrs[i + 1], i2 = g_csrs[i + 2], i3 = g_csrs[i + 3];
        float q0 = g_q[i0], q1 = g_q[i1], q2 = g_q[i2], q3 = g_q[i3];
        float4 u0 = *(const float4*)(g_h + i0 * DO + q * 4);
        float4 u1 = *(const float4*)(g_h + i1 * DO + q * 4);
        float4 u2 = *(const float4*)(g_h + i2 * DO + q * 4);
        float4 u3 = *(const float4*)(g_h + i3 * DO + q * 4);
        bx0 += q0 * u0.x + q2 * u2.x; by0 += q0 * u0.y + q2 * u2.y;
        bz0 += q0 * u0.z + q2 * u2.z; bw0 += q0 * u0.w + q2 * u2.w;
        bx1 += q1 * u1.x + q3 * u3.x; by1 += q1 * u1.y + q3 * u3.y;
        bz1 += q1 * u1.z + q3 * u3.z; bw1 += q1 * u1.w + q3 * u3.w;
        Qs += (q0 + q1) + (q2 + q3);
    }
    for (; i < end; i++) {
        int i0 = g_csrs[i];
        float q0 = g_q[i0];
        float4 u0 = *(const float4*)(g_h + i0 * DO + q * 4);
        bx0 += q0 * u0.x; by0 += q0 * u0.y; bz0 += q0 * u0.z; bw0 += q0 * u0.w;
        Qs += q0;
    }
    float bx = bx0 + bx1, by = by0 + by1, bz = bz0 + bz1, bw = bw0 + bw1;
    float4 hv = *(const float4*)(g_h + v * DO + q * 4);
    float4 Av = *(const float4*)(g_A + v * DO + q * 4);
    float qv = g_q[v];
    float dg = (float)g_degd[v];
    float w2 = 2.f * wgt[0];
    float4 o;
    o.x = hv.x + w2 * (qv * (dg * hv.x - Av.x) + Qs * hv.x - bx);
    o.y = hv.y + w2 * (qv * (dg * hv.y - Av.y) + Qs * hv.y - by);
    o.z = hv.z + w2 * (qv * (dg * hv.z - Av.z) + Qs * hv.z - bz);
    o.w = hv.w + w2 * (qv * (dg * hv.w - Av.w) + Qs * hv.w - bw);
    *(float4*)(out + v * DO + q * 4) = o;
}

// ---------------- launch ----------------------------------------------------
extern "C" void kernel_launch(void* const* d_in, const int* in_sizes, int n_in,
                              void* d_out, int out_size) {
    const float* x    = (const float*)d_in[0];
    const int*   ei   = (const int*)d_in[1];
    const float* wgt  = (const float*)d_in[2];
    const float* temp = (const float*)d_in[3];
    const float* W    = (const float*)d_in[4];
    const float* b    = (const float*)d_in[5];
    float* out = (float*)d_out;

    static cudaStream_t s2 = nullptr, s3 = nullptr;
    static cudaEvent_t evA = nullptr, evB = nullptr, evC = nullptr, evD = nullptr;
    if (s2 == nullptr) {
        cudaStreamCreateWithFlags(&s2, cudaStreamNonBlocking);
        cudaStreamCreateWithFlags(&s3, cudaStreamNonBlocking);
        cudaEventCreateWithFlags(&evA, cudaEventDisableTiming);
        cudaEventCreateWithFlags(&evB, cudaEventDisableTiming);
        cudaEventCreateWithFlags(&evC, cudaEventDisableTiming);
        cudaEventCreateWithFlags(&evD, cudaEventDisableTiming);
    }

    const int NB_E   = (NE + 255) / 256;
    const int NB_E4  = (NE / 4 + 255) / 256;
    const int NB_N   = (NN + 255) / 256;
    const int NB_N16 = (NN * 16 + 255) / 256;

    // fork: GEMM on side stream s2
    cudaEventRecord(evA, 0);
    cudaStreamWaitEvent(s2, evA, 0);
    k_gemm<<<(NN + 127) / 128, 128, 0, s2>>>(x, W);
    cudaEventRecord(evB, s2);

    // CSR build on main stream
    k_zero<<<NB_N, 256>>>();
    k_deg<<<NB_E4, 256>>>(ei);
    k_scan1<<<NBLK_SCAN, SB>>>();
    k_scan3<<<NB_N, 256>>>();
    cudaEventRecord(evD, 0);
    k_fill_d<<<NB_E, 256>>>(ei);

    // src-CSR fill on s3, overlapped with pass1/pass2
    cudaStreamWaitEvent(s3, evD, 0);
    k_fill_s<<<NB_E, 256, 0, s3>>>(ei);
    cudaEventRecord(evC, s3);

    // join GEMM
    cudaStreamWaitEvent(0, evB, 0);
    k_pass1<<<NB_N16, 256>>>(b);
    k_pass2<<<NB_N16, 256>>>(temp);
    k_q<<<NB_N, 256>>>(temp);

    // join src-CSR
    cudaStreamWaitEvent(0, evC, 0);
    k_pass3<<<NB_N16, 256>>>(wgt, out);
}

// round 12
// speedup vs baseline: 1.0462x; 1.0462x over previous
#include <cuda_runtime.h>

#define NN 100000
#define NE 1000000
#define DI 128
#define DO 64
#define SB 1024
#define NBLK_SCAN ((NN + SB - 1) / SB)   // 98
#define NBP2 ((NN * 16) / 256)           // 6250 pass2 blocks, exact
#define FULLM 0xffffffffu

// ---------------- scratch (device globals) ----------------------------------
__device__ float g_h0[NN * DO];
__device__ float g_h [NN * DO];
__device__ float g_A [NN * DO];
__device__ int   g_degd[NN];
__device__ int   g_degs[NN];
__device__ int   g_offd[NN + 1];
__device__ int   g_offs[NN + 1];
__device__ int   g_curd[NN];
__device__ int   g_curs[NN];
__device__ int   g_csrd[NE];
__device__ int   g_csrs[NE];
__device__ int   g_bsumd[NBLK_SCAN + 1];
__device__ int   g_bsums[NBLK_SCAN + 1];
__device__ float g_e[NN];
__device__ float g_nh[NN];
__device__ float g_q[NN];
__device__ float g_dinv[NN];
__device__ float g_pm[NBP2];
__device__ float g_pz[NBP2];
__device__ float g_pt[NBP2];

// ---------------- CSR build --------------------------------------------------
__global__ __launch_bounds__(256) void k_zero() {
    int i = blockIdx.x * 256 + threadIdx.x;
    if (i < NN) { g_degd[i] = 0; g_degs[i] = 0; }
}

__global__ __launch_bounds__(256) void k_deg(const int* __restrict__ ei) {
    int e2 = blockIdx.x * 256 + threadIdx.x;
    int e = e2 * 2;
    if (e + 1 < NE) {
        int2 s = *(const int2*)(ei + e);
        int2 d = *(const int2*)(ei + NE + e);
        atomicAdd(&g_degs[s.x], 1);
        atomicAdd(&g_degs[s.y], 1);
        atomicAdd(&g_degd[d.x], 1);
        atomicAdd(&g_degd[d.y], 1);
    } else if (e < NE) {
        atomicAdd(&g_degs[ei[e]], 1);
        atomicAdd(&g_degd[ei[NE + e]], 1);
    }
}

__global__ __launch_bounds__(SB) void k_scan1() {
    __shared__ int sd[SB], ss[SB];
    int t = threadIdx.x;
    int i = blockIdx.x * SB + t;
    int a = (i < NN) ? g_degd[i] : 0;
    int b = (i < NN) ? g_degs[i] : 0;
    sd[t] = a; ss[t] = b;
    __syncthreads();
    for (int o = 1; o < SB; o <<= 1) {
        int va = (t >= o) ? sd[t - o] : 0;
        int vb = (t >= o) ? ss[t - o] : 0;
        __syncthreads();
        sd[t] += va; ss[t] += vb;
        __syncthreads();
    }
    if (i < NN) { g_offd[i] = sd[t] - a; g_offs[i] = ss[t] - b; }
    if (t == SB - 1) { g_bsumd[blockIdx.x] = sd[t]; g_bsums[blockIdx.x] = ss[t]; }
}

// scan2 fused into scan3: each block redundantly scans the 98 block sums
__global__ __launch_bounds__(256) void k_scan3() {
    __shared__ int pd[128], ps[128];
    int t = threadIdx.x;
    if (t < 128) {
        pd[t] = (t < NBLK_SCAN) ? g_bsumd[t] : 0;
        ps[t] = (t < NBLK_SCAN) ? g_bsums[t] : 0;
    }
    __syncthreads();
    for (int o = 1; o < 128; o <<= 1) {
        int va = 0, vb = 0;
        if (t < 128 && t >= o) { va = pd[t - o]; vb = ps[t - o]; }
        __syncthreads();
        if (t < 128) { pd[t] += va; ps[t] += vb; }
        __syncthreads();
    }
    int i = blockIdx.x * 256 + t;
    if (i < NN) {
        int blk = i / SB;
        int exd = (blk == 0) ? 0 : pd[blk - 1];
        int exs = (blk == 0) ? 0 : ps[blk - 1];
        int od = g_offd[i] + exd;
        int os = g_offs[i] + exs;
        g_offd[i] = od; g_curd[i] = od;
        g_offs[i] = os; g_curs[i] = os;
        g_dinv[i] = rsqrtf((float)(g_degd[i] + 1));
    }
    if (i == 0) { g_offd[NN] = NE; g_offs[NN] = NE; }
}

__global__ __launch_bounds__(256) void k_fill_d(const int* __restrict__ ei) {
    int e = blockIdx.x * 256 + threadIdx.x;
    if (e >= NE) return;
    int s = ei[e], d = ei[NE + e];
    int pd = atomicAdd(&g_curd[d], 1);
    g_csrd[pd] = s;
}

__global__ __launch_bounds__(256) void k_fill_s(const int* __restrict__ ei) {
    int e = blockIdx.x * 256 + threadIdx.x;
    if (e >= NE) return;
    int s = ei[e], d = ei[NE + e];
    int ps = atomicAdd(&g_curs[s], 1);
    g_csrs[ps] = d;
}

// ---------------- GEMM: h0 = x @ W (128 rows/block, 8x8 per thread) ----------
__global__ __launch_bounds__(128) void k_gemm(const float* __restrict__ x,
                                              const float* __restrict__ W) {
    __shared__ float Ws[DI * DO];
    __shared__ float xs[16 * 128];
    int t = threadIdx.x;
    int row0 = blockIdx.x * 128;
    for (int i = t * 4; i < DI * DO; i += 128 * 4)
        *(float4*)(Ws + i) = *(const float4*)(W + i);

    int cg = t & 7, rt = t >> 3;
    float acc[8][8];
#pragma unroll
    for (int i = 0; i < 8; i++)
#pragma unroll
        for (int j = 0; j < 8; j++) acc[i][j] = 0.f;

    int grow = row0 + t;
    bool rok = grow < NN;

    for (int kc = 0; kc < 8; kc++) {
        __syncthreads();
        float4 xa = rok ? *(const float4*)(x + grow * DI + kc * 16 + 0)  : make_float4(0,0,0,0);
        float4 xb = rok ? *(const float4*)(x + grow * DI + kc * 16 + 4)  : make_float4(0,0,0,0);
        float4 xc = rok ? *(const float4*)(x + grow * DI + kc * 16 + 8)  : make_float4(0,0,0,0);
        float4 xd = rok ? *(const float4*)(x + grow * DI + kc * 16 + 12) : make_float4(0,0,0,0);
        xs[0*128+t]=xa.x;  xs[1*128+t]=xa.y;  xs[2*128+t]=xa.z;  xs[3*128+t]=xa.w;
        xs[4*128+t]=xb.x;  xs[5*128+t]=xb.y;  xs[6*128+t]=xb.z;  xs[7*128+t]=xb.w;
        xs[8*128+t]=xc.x;  xs[9*128+t]=xc.y;  xs[10*128+t]=xc.z; xs[11*128+t]=xc.w;
        xs[12*128+t]=xd.x; xs[13*128+t]=xd.y; xs[14*128+t]=xd.z; xs[15*128+t]=xd.w;
        __syncthreads();
#pragma unroll
        for (int k = 0; k < 16; k++) {
            float4 x0 = *(const float4*)(xs + k * 128 + rt * 8);
            float4 x1 = *(const float4*)(xs + k * 128 + rt * 8 + 4);
            float4 w0 = *(const float4*)(Ws + (kc * 16 + k) * DO + cg * 8);
            float4 w1 = *(const float4*)(Ws + (kc * 16 + k) * DO + cg * 8 + 4);
            float xv[8] = {x0.x, x0.y, x0.z, x0.w, x1.x, x1.y, x1.z, x1.w};
            float wv[8] = {w0.x, w0.y, w0.z, w0.w, w1.x, w1.y, w1.z, w1.w};
#pragma unroll
            for (int i = 0; i < 8; i++)
#pragma unroll
                for (int j = 0; j < 8; j++)
                    acc[i][j] += xv[i] * wv[j];
        }
    }
#pragma unroll
    for (int i = 0; i < 8; i++) {
        int gr = row0 + rt * 8 + i;
        if (gr < NN) {
            float4* p = (float4*)(g_h0 + gr * DO + cg * 8);
            p[0] = make_float4(acc[i][0], acc[i][1], acc[i][2], acc[i][3]);
            p[1] = make_float4(acc[i][4], acc[i][5], acc[i][6], acc[i][7]);
        }
    }
}

// ---------------- online triple helper ----------------------------------------
__device__ __forceinline__ void triple_merge(float& m, float& z, float& t,
                                             float m2, float z2, float t2) {
    float M = fmaxf(m, m2);
    float a = expf(m - M), c = expf(m2 - M);
    z = z * a + z2 * c;
    t = t * a + t2 * c;
    m = M;
}

// ---------------- gather passes (16 lanes/node, 2-edge unroll w/ prefetch) ----
__global__ __launch_bounds__(256) void k_pass1(const float* __restrict__ b) {
    int t = blockIdx.x * 256 + threadIdx.x;
    int v = t >> 4, q = t & 15;
    if (v >= NN) return;
    int start = g_offd[v], end = g_offd[v + 1];
    float ax0 = 0.f, ay0 = 0.f, az0 = 0.f, aw0 = 0.f;
    float ax1 = 0.f, ay1 = 0.f, az1 = 0.f, aw1 = 0.f;
    int i = start;
    int idx0 = (i     < end) ? g_csrd[i]     : 0;
    int idx1 = (i + 1 < end) ? g_csrd[i + 1] : 0;
    for (; i + 1 < end; i += 2) {
        int n0 = (i + 2 < end) ? g_csrd[i + 2] : 0;
        int n1 = (i + 3 < end) ? g_csrd[i + 3] : 0;
        float d0 = g_dinv[idx0], d1 = g_dinv[idx1];
        float4 u0 = *(const float4*)(g_h0 + idx0 * DO + q * 4);
        float4 u1 = *(const float4*)(g_h0 + idx1 * DO + q * 4);
        ax0 += u0.x * d0; ay0 += u0.y * d0; az0 += u0.z * d0; aw0 += u0.w * d0;
        ax1 += u1.x * d1; ay1 += u1.y * d1; az1 += u1.z * d1; aw1 += u1.w * d1;
        idx0 = n0; idx1 = n1;
    }
    if (i < end) {
        float d0 = g_dinv[idx0];
        float4 u0 = *(const float4*)(g_h0 + idx0 * DO + q * 4);
        ax0 += u0.x * d0; ay0 += u0.y * d0; az0 += u0.z * d0; aw0 += u0.w * d0;
    }
    float ax = ax0 + ax1, ay = ay0 + ay1, az = az0 + az1, aw = aw0 + aw1;
    float dv = g_dinv[v];
    float dv2 = dv * dv;
    float4 h0v = *(const float4*)(g_h0 + v * DO + q * 4);
    float4 bv  = *(const float4*)(b + q * 4);
    float4 h;
    h.x = dv * ax + dv2 * h0v.x + bv.x;
    h.y = dv * ay + dv2 * h0v.y + bv.y;
    h.z = dv * az + dv2 * h0v.z + bv.z;
    h.w = dv * aw + dv2 * h0v.w + bv.w;
    *(float4*)(g_h + v * DO + q * 4) = h;
    float p = h.x * h.x + h.y * h.y + h.z * h.z + h.w * h.w;
#pragma unroll
    for (int off = 8; off; off >>= 1)
        p += __shfl_down_sync(FULLM, p, off, 16);
    if (q == 0) g_nh[v] = p;
}

// pass2 + per-block softmax triple (exactly 16 nodes per block; grid exact)
__global__ __launch_bounds__(256) void k_pass2(const float* __restrict__ temp) {
    __shared__ float se[16];
    int t = blockIdx.x * 256 + threadIdx.x;
    int v = t >> 4, q = t & 15;
    int start = g_offd[v], end = g_offd[v + 1];
    float ax0 = 0.f, ay0 = 0.f, az0 = 0.f, aw0 = 0.f;
    float ax1 = 0.f, ay1 = 0.f, az1 = 0.f, aw1 = 0.f;
    float es = 0.f;
    int i = start;
    int idx0 = (i     < end) ? g_csrd[i]     : 0;
    int idx1 = (i + 1 < end) ? g_csrd[i + 1] : 0;
    for (; i + 1 < end; i += 2) {
        int n0 = (i + 2 < end) ? g_csrd[i + 2] : 0;
        int n1 = (i + 3 < end) ? g_csrd[i + 3] : 0;
        float4 u0 = *(const float4*)(g_h + idx0 * DO + q * 4);
        float4 u1 = *(const float4*)(g_h + idx1 * DO + q * 4);
        ax0 += u0.x; ay0 += u0.y; az0 += u0.z; aw0 += u0.w;
        ax1 += u1.x; ay1 += u1.y; az1 += u1.z; aw1 += u1.w;
        if (q == 0) es += g_nh[idx0] + g_nh[idx1];
        idx0 = n0; idx1 = n1;
    }
    if (i < end) {
        float4 u0 = *(const float4*)(g_h + idx0 * DO + q * 4);
        ax0 += u0.x; ay0 += u0.y; az0 += u0.z; aw0 += u0.w;
        if (q == 0) es += g_nh[idx0];
    }
    float ax = ax0 + ax1, ay = ay0 + ay1, az = az0 + az1, aw = aw0 + aw1;
    *(float4*)(g_A + v * DO + q * 4) = make_float4(ax, ay, az, aw);
    float4 hv = *(const float4*)(g_h + v * DO + q * 4);
    float p = hv.x * ax + hv.y * ay + hv.z * az + hv.w * aw;
#pragma unroll
    for (int off = 8; off; off >>= 1)
        p += __shfl_down_sync(FULLM, p, off, 16);
    if (q == 0) {
        float e = (float)g_degd[v] * g_nh[v] - 2.f * p + es;
        g_e[v] = e;
        se[threadIdx.x >> 4] = e;
    }
    __syncthreads();
    if (threadIdx.x < 16) {
        float tmp = temp[0];
        float m = -se[threadIdx.x] / tmp;
        float z = 1.f, tt = m;
#pragma unroll
        for (int off = 8; off; off >>= 1) {
            float m2 = __shfl_down_sync(0x0000ffffu, m, off, 16);
            float z2 = __shfl_down_sync(0x0000ffffu, z, off, 16);
            float t2 = __shfl_down_sync(0x0000ffffu, tt, off, 16);
            triple_merge(m, z, tt, m2, z2, t2);
        }
        if (threadIdx.x == 0) {
            g_pm[blockIdx.x] = m; g_pz[blockIdx.x] = z; g_pt[blockIdx.x] = tt;
        }
    }
}

// merge all block triples, compute q
__global__ __launch_bounds__(256) void k_q(const float* __restrict__ temp) {
    __shared__ float sm[256], sz[256], st[256];
    int tx = threadIdx.x;
    float m = -1e30f, z = 0.f, t = 0.f;
    for (int j = tx; j < NBP2; j += 256)
        triple_merge(m, z, t, g_pm[j], g_pz[j], g_pt[j]);
    sm[tx] = m; sz[tx] = z; st[tx] = t;
    __syncthreads();
    for (int o = 128; o; o >>= 1) {
        if (tx < o) {
            float mm = sm[tx], zz = sz[tx], tt = st[tx];
            triple_merge(mm, zz, tt, sm[tx + o], sz[tx + o], st[tx + o]);
            sm[tx] = mm; sz[tx] = zz; st[tx] = tt;
        }
        __syncthreads();
    }
    float M = sm[0], Z = sz[0], T = st[0];
    float invZ = 1.f / Z;
    float L = M + logf(Z);
    float H = L - T * invZ;
    int v = blockIdx.x * 256 + tx;
    if (v >= NN) return;
    float tmp = temp[0];
    float s = -g_e[v] / tmp;
    g_q[v] = expf(s - M) * invZ * (s - L + H);
}

// pass3 + final (16 lanes/node, 2-edge unroll w/ prefetch)
__global__ __launch_bounds__(256) void k_pass3(const float* __restrict__ wgt,
                                               float* __restrict__ out) {
    int t = blockIdx.x * 256 + threadIdx.x;
    int v = t >> 4, q = t & 15;
    if (v >= NN) return;
    int start = g_offs[v], end = g_offs[v + 1];
    float bx0 = 0.f, by0 = 0.f, bz0 = 0.f, bw0 = 0.f;
    float bx1 = 0.f, by1 = 0.f, bz1 = 0.f, bw1 = 0.f;
    float Qs = 0.f;
    int i = start;
    int idx0 = (i     < end) ? g_csrs[i]     : 0;
    int idx1 = (i + 1 < end) ? g_csrs[i + 1] : 0;
    for (; i + 1 < end; i += 2) {
        int n0 = (i + 2 < end) ? g_csrs[i + 2] : 0;
        int n1 = (i + 3 < end) ? g_csrs[i + 3] : 0;
        float q0 = g_q[idx0], q1 = g_q[idx1];
        float4 u0 = *(const float4*)(g_h + idx0 * DO + q * 4);
        float4 u1 = *(const float4*)(g_h + idx1 * DO + q * 4);
        bx0 += q0 * u0.x; by0 += q0 * u0.y; bz0 += q0 * u0.z; bw0 += q0 * u0.w;
        bx1 += q1 * u1.x; by1 += q1 * u1.y; bz1 += q1 * u1.z; bw1 += q1 * u1.w;
        Qs += q0 + q1;
        idx0 = n0; idx1 = n1;
    }
    if (i < end) {
        float q0 = g_q[idx0];
        float4 u0 = *(const float4*)(g_h + idx0 * DO + q * 4);
        bx0 += q0 * u0.x; by0 += q0 * u0.y; bz0 += q0 * u0.z; bw0 += q0 * u0.w;
        Qs += q0;
    }
    float bx = bx0 + bx1, by = by0 + by1, bz = bz0 + bz1, bw = bw0 + bw1;
    float4 hv = *(const float4*)(g_h + v * DO + q * 4);
    float4 Av = *(const float4*)(g_A + v * DO + q * 4);
    float qv = g_q[v];
    float dg = (float)g_degd[v];
    float w2 = 2.f * wgt[0];
    float4 o;
    o.x = hv.x + w2 * (qv * (dg * hv.x - Av.x) + Qs * hv.x - bx);
    o.y = hv.y + w2 * (qv * (dg * hv.y - Av.y) + Qs * hv.y - by);
    o.z = hv.z + w2 * (qv * (dg * hv.z - Av.z) + Qs * hv.z - bz);
    o.w = hv.w + w2 * (qv * (dg * hv.w - Av.w) + Qs * hv.w - bw);
    *(float4*)(out + v * DO + q * 4) = o;
}

// ---------------- launch ----------------------------------------------------
extern "C" void kernel_launch(void* const* d_in, const int* in_sizes, int n_in,
                              void* d_out, int out_size) {
    const float* x    = (const float*)d_in[0];
    const int*   ei   = (const int*)d_in[1];
    const float* wgt  = (const float*)d_in[2];
    const float* temp = (const float*)d_in[3];
    const float* W    = (const float*)d_in[4];
    const float* b    = (const float*)d_in[5];
    float* out = (float*)d_out;

    static cudaStream_t s2 = nullptr, s3 = nullptr;
    static cudaEvent_t evA = nullptr, evB = nullptr, evC = nullptr, evD = nullptr;
    if (s2 == nullptr) {
        cudaStreamCreateWithFlags(&s2, cudaStreamNonBlocking);
        cudaStreamCreateWithFlags(&s3, cudaStreamNonBlocking);
        cudaEventCreateWithFlags(&evA, cudaEventDisableTiming);
        cudaEventCreateWithFlags(&evB, cudaEventDisableTiming);
        cudaEventCreateWithFlags(&evC, cudaEventDisableTiming);
        cudaEventCreateWithFlags(&evD, cudaEventDisableTiming);
    }

    const int NB_E   = (NE + 255) / 256;
    const int NB_E2  = (NE / 2 + 255) / 256;
    const int NB_N   = (NN + 255) / 256;
    const int NB_N16 = (NN * 16 + 255) / 256;

    // fork: GEMM on side stream s2
    cudaEventRecord(evA, 0);
    cudaStreamWaitEvent(s2, evA, 0);
    k_gemm<<<(NN + 127) / 128, 128, 0, s2>>>(x, W);
    cudaEventRecord(evB, s2);

    // CSR build on main stream
    k_zero<<<NB_N, 256>>>();
    k_deg<<<NB_E2, 256>>>(ei);
    k_scan1<<<NBLK_SCAN, SB>>>();
    k_scan3<<<NB_N, 256>>>();
    cudaEventRecord(evD, 0);
    k_fill_d<<<NB_E, 256>>>(ei);

    // src-CSR fill on s3, overlapped with pass1/pass2
    cudaStreamWaitEvent(s3, evD, 0);
    k_fill_s<<<NB_E, 256, 0, s3>>>(ei);
    cudaEventRecord(evC, s3);

    // join GEMM
    cudaStreamWaitEvent(0, evB, 0);
    k_pass1<<<NB_N16, 256>>>(b);
    k_pass2<<<NB_N16, 256>>>(temp);
    k_q<<<NB_N, 256>>>(temp);

    // join src-CSR
    cudaStreamWaitEvent(0, evC, 0);
    k_pass3<<<NB_N16, 256>>>(wgt, out);
}

// round 13
// speedup vs baseline: 1.0756x; 1.0281x over previous
#include <cuda_runtime.h>

#define NN 100000
#define NE 1000000
#define DI 128
#define DO 64
#define SB 1024
#define NBLK_SCAN ((NN + SB - 1) / SB)   // 98
#define NSUMB 256
#define FULLM 0xffffffffu

// ---------------- scratch (device globals) ----------------------------------
__device__ float g_h0[NN * DO];
__device__ float g_h [NN * DO];
__device__ float g_A [NN * DO];
__device__ int   g_degd[NN];
__device__ int   g_degs[NN];
__device__ int   g_offd[NN + 1];
__device__ int   g_offs[NN + 1];
__device__ int   g_curd[NN];
__device__ int   g_curs[NN];
__device__ int   g_csrd[NE];
__device__ int   g_csrs[NE];
__device__ int   g_bsumd[NBLK_SCAN + 1];
__device__ int   g_bsums[NBLK_SCAN + 1];
__device__ float g_e[NN];
__device__ float g_nh[NN];
__device__ float g_q[NN];
__device__ float g_dinv[NN];
__device__ float g_pm[NSUMB];
__device__ float g_pz[NSUMB];
__device__ float g_pt[NSUMB];

// ---------------- CSR build --------------------------------------------------
__global__ __launch_bounds__(256) void k_zero() {
    int i = blockIdx.x * 256 + threadIdx.x;
    if (i < NN) { g_degd[i] = 0; g_degs[i] = 0; }
}

__global__ __launch_bounds__(256) void k_deg(const int* __restrict__ ei) {
    int e2 = blockIdx.x * 256 + threadIdx.x;
    int e = e2 * 2;
    if (e + 1 < NE) {
        int2 s = *(const int2*)(ei + e);
        int2 d = *(const int2*)(ei + NE + e);
        atomicAdd(&g_degs[s.x], 1);
        atomicAdd(&g_degs[s.y], 1);
        atomicAdd(&g_degd[d.x], 1);
        atomicAdd(&g_degd[d.y], 1);
    } else if (e < NE) {
        atomicAdd(&g_degs[ei[e]], 1);
        atomicAdd(&g_degd[ei[NE + e]], 1);
    }
}

__global__ __launch_bounds__(SB) void k_scan1() {
    __shared__ int sd[SB], ss[SB];
    int t = threadIdx.x;
    int i = blockIdx.x * SB + t;
    int a = (i < NN) ? g_degd[i] : 0;
    int b = (i < NN) ? g_degs[i] : 0;
    sd[t] = a; ss[t] = b;
    __syncthreads();
    for (int o = 1; o < SB; o <<= 1) {
        int va = (t >= o) ? sd[t - o] : 0;
        int vb = (t >= o) ? ss[t - o] : 0;
        __syncthreads();
        sd[t] += va; ss[t] += vb;
        __syncthreads();
    }
    if (i < NN) { g_offd[i] = sd[t] - a; g_offs[i] = ss[t] - b; }
    if (t == SB - 1) { g_bsumd[blockIdx.x] = sd[t]; g_bsums[blockIdx.x] = ss[t]; }
}

// scan2 fused into scan3: each block redundantly scans the 98 block sums
__global__ __launch_bounds__(256) void k_scan3() {
    __shared__ int pd[128], ps[128];
    int t = threadIdx.x;
    if (t < 128) {
        pd[t] = (t < NBLK_SCAN) ? g_bsumd[t] : 0;
        ps[t] = (t < NBLK_SCAN) ? g_bsums[t] : 0;
    }
    __syncthreads();
    for (int o = 1; o < 128; o <<= 1) {
        int va = 0, vb = 0;
        if (t < 128 && t >= o) { va = pd[t - o]; vb = ps[t - o]; }
        __syncthreads();
        if (t < 128) { pd[t] += va; ps[t] += vb; }
        __syncthreads();
    }
    int i = blockIdx.x * 256 + t;
    if (i < NN) {
        int blk = i / SB;
        int exd = (blk == 0) ? 0 : pd[blk - 1];
        int exs = (blk == 0) ? 0 : ps[blk - 1];
        int od = g_offd[i] + exd;
        int os = g_offs[i] + exs;
        g_offd[i] = od; g_curd[i] = od;
        g_offs[i] = os; g_curs[i] = os;
        g_dinv[i] = rsqrtf((float)(g_degd[i] + 1));
    }
    if (i == 0) { g_offd[NN] = NE; g_offs[NN] = NE; }
}

__global__ __launch_bounds__(256) void k_fill_d(const int* __restrict__ ei) {
    int e = blockIdx.x * 256 + threadIdx.x;
    if (e >= NE) return;
    int s = ei[e], d = ei[NE + e];
    int pd = atomicAdd(&g_curd[d], 1);
    g_csrd[pd] = s;
}

__global__ __launch_bounds__(256) void k_fill_s(const int* __restrict__ ei) {
    int e = blockIdx.x * 256 + threadIdx.x;
    if (e >= NE) return;
    int s = ei[e], d = ei[NE + e];
    int ps = atomicAdd(&g_curs[s], 1);
    g_csrs[ps] = d;
}

// ---------------- GEMM: h0 = x @ W (256 rows/block, 256 thr, 8x8/thread) -----
__global__ __launch_bounds__(256) void k_gemm(const float* __restrict__ x,
                                              const float* __restrict__ W) {
    __shared__ float Ws[DI * DO];     // 32 KB
    __shared__ float xs[16 * 256];    // 16 KB
    int t = threadIdx.x;
    int row0 = blockIdx.x * 256;
    for (int i = t * 4; i < DI * DO; i += 256 * 4)
        *(float4*)(Ws + i) = *(const float4*)(W + i);

    int cg = t & 7;          // cols cg*8 .. cg*8+7
    int rt = t >> 3;         // 0..31 -> rows rt*8 .. rt*8+7
    float acc[8][8];
#pragma unroll
    for (int i = 0; i < 8; i++)
#pragma unroll
        for (int j = 0; j < 8; j++) acc[i][j] = 0.f;

    int grow = row0 + t;     // thread t stages row t of this block
    bool rok = grow < NN;

    for (int kc = 0; kc < 8; kc++) {
        __syncthreads();
        float4 xa = rok ? *(const float4*)(x + grow * DI + kc * 16 + 0)  : make_float4(0,0,0,0);
        float4 xb = rok ? *(const float4*)(x + grow * DI + kc * 16 + 4)  : make_float4(0,0,0,0);
        float4 xc = rok ? *(const float4*)(x + grow * DI + kc * 16 + 8)  : make_float4(0,0,0,0);
        float4 xd = rok ? *(const float4*)(x + grow * DI + kc * 16 + 12) : make_float4(0,0,0,0);
        xs[0*256+t]=xa.x;  xs[1*256+t]=xa.y;  xs[2*256+t]=xa.z;  xs[3*256+t]=xa.w;
        xs[4*256+t]=xb.x;  xs[5*256+t]=xb.y;  xs[6*256+t]=xb.z;  xs[7*256+t]=xb.w;
        xs[8*256+t]=xc.x;  xs[9*256+t]=xc.y;  xs[10*256+t]=xc.z; xs[11*256+t]=xc.w;
        xs[12*256+t]=xd.x; xs[13*256+t]=xd.y; xs[14*256+t]=xd.z; xs[15*256+t]=xd.w;
        __syncthreads();
#pragma unroll
        for (int k = 0; k < 16; k++) {
            float4 x0 = *(const float4*)(xs + k * 256 + rt * 8);
            float4 x1 = *(const float4*)(xs + k * 256 + rt * 8 + 4);
            float4 w0 = *(const float4*)(Ws + (kc * 16 + k) * DO + cg * 8);
            float4 w1 = *(const float4*)(Ws + (kc * 16 + k) * DO + cg * 8 + 4);
            float xv[8] = {x0.x, x0.y, x0.z, x0.w, x1.x, x1.y, x1.z, x1.w};
            float wv[8] = {w0.x, w0.y, w0.z, w0.w, w1.x, w1.y, w1.z, w1.w};
#pragma unroll
            for (int i = 0; i < 8; i++)
#pragma unroll
                for (int j = 0; j < 8; j++)
                    acc[i][j] += xv[i] * wv[j];
        }
    }
#pragma unroll
    for (int i = 0; i < 8; i++) {
        int gr = row0 + rt * 8 + i;
        if (gr < NN) {
            float4* p = (float4*)(g_h0 + gr * DO + cg * 8);
            p[0] = make_float4(acc[i][0], acc[i][1], acc[i][2], acc[i][3]);
            p[1] = make_float4(acc[i][4], acc[i][5], acc[i][6], acc[i][7]);
        }
    }
}

// ---------------- gather passes (16 lanes/node, 2-edge unroll w/ prefetch) ----
__global__ __launch_bounds__(256) void k_pass1(const float* __restrict__ b) {
    int t = blockIdx.x * 256 + threadIdx.x;
    int v = t >> 4, q = t & 15;
    if (v >= NN) return;
    int start = g_offd[v], end = g_offd[v + 1];
    float ax0 = 0.f, ay0 = 0.f, az0 = 0.f, aw0 = 0.f;
    float ax1 = 0.f, ay1 = 0.f, az1 = 0.f, aw1 = 0.f;
    int i = start;
    int idx0 = (i     < end) ? g_csrd[i]     : 0;
    int idx1 = (i + 1 < end) ? g_csrd[i + 1] : 0;
    for (; i + 1 < end; i += 2) {
        int n0 = (i + 2 < end) ? g_csrd[i + 2] : 0;
        int n1 = (i + 3 < end) ? g_csrd[i + 3] : 0;
        float d0 = g_dinv[idx0], d1 = g_dinv[idx1];
        float4 u0 = *(const float4*)(g_h0 + idx0 * DO + q * 4);
        float4 u1 = *(const float4*)(g_h0 + idx1 * DO + q * 4);
        ax0 += u0.x * d0; ay0 += u0.y * d0; az0 += u0.z * d0; aw0 += u0.w * d0;
        ax1 += u1.x * d1; ay1 += u1.y * d1; az1 += u1.z * d1; aw1 += u1.w * d1;
        idx0 = n0; idx1 = n1;
    }
    if (i < end) {
        float d0 = g_dinv[idx0];
        float4 u0 = *(const float4*)(g_h0 + idx0 * DO + q * 4);
        ax0 += u0.x * d0; ay0 += u0.y * d0; az0 += u0.z * d0; aw0 += u0.w * d0;
    }
    float ax = ax0 + ax1, ay = ay0 + ay1, az = az0 + az1, aw = aw0 + aw1;
    float dv = g_dinv[v];
    float dv2 = dv * dv;
    float4 h0v = *(const float4*)(g_h0 + v * DO + q * 4);
    float4 bv  = *(const float4*)(b + q * 4);
    float4 h;
    h.x = dv * ax + dv2 * h0v.x + bv.x;
    h.y = dv * ay + dv2 * h0v.y + bv.y;
    h.z = dv * az + dv2 * h0v.z + bv.z;
    h.w = dv * aw + dv2 * h0v.w + bv.w;
    *(float4*)(g_h + v * DO + q * 4) = h;
    float p = h.x * h.x + h.y * h.y + h.z * h.z + h.w * h.w;
#pragma unroll
    for (int off = 8; off; off >>= 1)
        p += __shfl_down_sync(FULLM, p, off, 16);
    if (q == 0) g_nh[v] = p;
}

__global__ __launch_bounds__(256) void k_pass2() {
    int t = blockIdx.x * 256 + threadIdx.x;
    int v = t >> 4, q = t & 15;
    if (v >= NN) return;
    int start = g_offd[v], end = g_offd[v + 1];
    float ax0 = 0.f, ay0 = 0.f, az0 = 0.f, aw0 = 0.f;
    float ax1 = 0.f, ay1 = 0.f, az1 = 0.f, aw1 = 0.f;
    float es = 0.f;
    int i = start;
    int idx0 = (i     < end) ? g_csrd[i]     : 0;
    int idx1 = (i + 1 < end) ? g_csrd[i + 1] : 0;
    for (; i + 1 < end; i += 2) {
        int n0 = (i + 2 < end) ? g_csrd[i + 2] : 0;
        int n1 = (i + 3 < end) ? g_csrd[i + 3] : 0;
        float4 u0 = *(const float4*)(g_h + idx0 * DO + q * 4);
        float4 u1 = *(const float4*)(g_h + idx1 * DO + q * 4);
        ax0 += u0.x; ay0 += u0.y; az0 += u0.z; aw0 += u0.w;
        ax1 += u1.x; ay1 += u1.y; az1 += u1.z; aw1 += u1.w;
        if (q == 0) es += g_nh[idx0] + g_nh[idx1];
        idx0 = n0; idx1 = n1;
    }
    if (i < end) {
        float4 u0 = *(const float4*)(g_h + idx0 * DO + q * 4);
        ax0 += u0.x; ay0 += u0.y; az0 += u0.z; aw0 += u0.w;
        if (q == 0) es += g_nh[idx0];
    }
    float ax = ax0 + ax1, ay = ay0 + ay1, az = az0 + az1, aw = aw0 + aw1;
    *(float4*)(g_A + v * DO + q * 4) = make_float4(ax, ay, az, aw);
    float4 hv = *(const float4*)(g_h + v * DO + q * 4);
    float p = hv.x * ax + hv.y * ay + hv.z * az + hv.w * aw;
#pragma unroll
    for (int off = 8; off; off >>= 1)
        p += __shfl_down_sync(FULLM, p, off, 16);
    if (q == 0)
        g_e[v] = (float)g_degd[v] * g_nh[v] - 2.f * p + es;
}

// ---------------- online softmax scalars --------------------------------------
__device__ __forceinline__ void triple_merge(float& m, float& z, float& t,
                                             float m2, float z2, float t2) {
    float M = fmaxf(m, m2);
    float a = expf(m - M), c = expf(m2 - M);
    z = z * a + z2 * c;
    t = t * a + t2 * c;
    m = M;
}

__global__ __launch_bounds__(256) void k_sum(const float* __restrict__ temp) {
    float tmp = temp[0];
    float m = -1e30f, z = 0.f, t = 0.f;
    for (int i = blockIdx.x * 256 + threadIdx.x; i < NN; i += NSUMB * 256) {
        float s = -g_e[i] / tmp;
        float M = fmaxf(m, s);
        float a = expf(m - M), c = expf(s - M);
        z = z * a + c;
        t = t * a + s * c;
        m = M;
    }
    __shared__ float sm[256], sz[256], st[256];
    sm[threadIdx.x] = m; sz[threadIdx.x] = z; st[threadIdx.x] = t;
    __syncthreads();
    for (int o = 128; o; o >>= 1) {
        if (threadIdx.x < o) {
            float mm = sm[threadIdx.x], zz = sz[threadIdx.x], tt = st[threadIdx.x];
            triple_merge(mm, zz, tt, sm[threadIdx.x + o], sz[threadIdx.x + o], st[threadIdx.x + o]);
            sm[threadIdx.x] = mm; sz[threadIdx.x] = zz; st[threadIdx.x] = tt;
        }
        __syncthreads();
    }
    if (threadIdx.x == 0) {
        g_pm[blockIdx.x] = sm[0]; g_pz[blockIdx.x] = sz[0]; g_pt[blockIdx.x] = st[0];
    }
}

__global__ __launch_bounds__(256) void k_q(const float* __restrict__ temp) {
    __shared__ float sm[256], sz[256], st[256];
    int tx = threadIdx.x;
    sm[tx] = g_pm[tx]; sz[tx] = g_pz[tx]; st[tx] = g_pt[tx];
    __syncthreads();
    for (int o = 128; o; o >>= 1) {
        if (tx < o) {
            float mm = sm[tx], zz = sz[tx], tt = st[tx];
            triple_merge(mm, zz, tt, sm[tx + o], sz[tx + o], st[tx + o]);
            sm[tx] = mm; sz[tx] = zz; st[tx] = tt;
        }
        __syncthreads();
    }
    float M = sm[0], Z = sz[0], T = st[0];
    float invZ = 1.f / Z;
    float L = M + logf(Z);
    float H = L - T * invZ;
    int v = blockIdx.x * 256 + tx;
    if (v >= NN) return;
    float tmp = temp[0];
    float s = -g_e[v] / tmp;
    g_q[v] = expf(s - M) * invZ * (s - L + H);
}

// pass3 + final (16 lanes/node, 2-edge unroll w/ prefetch)
__global__ __launch_bounds__(256) void k_pass3(const float* __restrict__ wgt,
                                               float* __restrict__ out) {
    int t = blockIdx.x * 256 + threadIdx.x;
    int v = t >> 4, q = t & 15;
    if (v >= NN) return;
    int start = g_offs[v], end = g_offs[v + 1];
    float bx0 = 0.f, by0 = 0.f, bz0 = 0.f, bw0 = 0.f;
    float bx1 = 0.f, by1 = 0.f, bz1 = 0.f, bw1 = 0.f;
    float Qs = 0.f;
    int i = start;
    int idx0 = (i     < end) ? g_csrs[i]     : 0;
    int idx1 = (i + 1 < end) ? g_csrs[i + 1] : 0;
    for (; i + 1 < end; i += 2) {
        int n0 = (i + 2 < end) ? g_csrs[i + 2] : 0;
        int n1 = (i + 3 < end) ? g_csrs[i + 3] : 0;
        float q0 = g_q[idx0], q1 = g_q[idx1];
        float4 u0 = *(const float4*)(g_h + idx0 * DO + q * 4);
        float4 u1 = *(const float4*)(g_h + idx1 * DO + q * 4);
        bx0 += q0 * u0.x; by0 += q0 * u0.y; bz0 += q0 * u0.z; bw0 += q0 * u0.w;
        bx1 += q1 * u1.x; by1 += q1 * u1.y; bz1 += q1 * u1.z; bw1 += q1 * u1.w;
        Qs += q0 + q1;
        idx0 = n0; idx1 = n1;
    }
    if (i < end) {
        float q0 = g_q[idx0];
        float4 u0 = *(const float4*)(g_h + idx0 * DO + q * 4);
        bx0 += q0 * u0.x; by0 += q0 * u0.y; bz0 += q0 * u0.z; bw0 += q0 * u0.w;
        Qs += q0;
    }
    float bx = bx0 + bx1, by = by0 + by1, bz = bz0 + bz1, bw = bw0 + bw1;
    float4 hv = *(const float4*)(g_h + v * DO + q * 4);
    float4 Av = *(const float4*)(g_A + v * DO + q * 4);
    float qv = g_q[v];
    float dg = (float)g_degd[v];
    float w2 = 2.f * wgt[0];
    float4 o;
    o.x = hv.x + w2 * (qv * (dg * hv.x - Av.x) + Qs * hv.x - bx);
    o.y = hv.y + w2 * (qv * (dg * hv.y - Av.y) + Qs * hv.y - by);
    o.z = hv.z + w2 * (qv * (dg * hv.z - Av.z) + Qs * hv.z - bz);
    o.w = hv.w + w2 * (qv * (dg * hv.w - Av.w) + Qs * hv.w - bw);
    *(float4*)(out + v * DO + q * 4) = o;
}

// ---------------- launch ----------------------------------------------------
extern "C" void kernel_launch(void* const* d_in, const int* in_sizes, int n_in,
                              void* d_out, int out_size) {
    const float* x    = (const float*)d_in[0];
    const int*   ei   = (const int*)d_in[1];
    const float* wgt  = (const float*)d_in[2];
    const float* temp = (const float*)d_in[3];
    const float* W    = (const float*)d_in[4];
    const float* b    = (const float*)d_in[5];
    float* out = (float*)d_out;

    static cudaStream_t s2 = nullptr, s3 = nullptr;
    static cudaEvent_t evA = nullptr, evB = nullptr, evC = nullptr, evD = nullptr;
    if (s2 == nullptr) {
        cudaStreamCreateWithFlags(&s2, cudaStreamNonBlocking);
        cudaStreamCreateWithFlags(&s3, cudaStreamNonBlocking);
        cudaEventCreateWithFlags(&evA, cudaEventDisableTiming);
        cudaEventCreateWithFlags(&evB, cudaEventDisableTiming);
        cudaEventCreateWithFlags(&evC, cudaEventDisableTiming);
        cudaEventCreateWithFlags(&evD, cudaEventDisableTiming);
    }

    const int NB_E   = (NE + 255) / 256;
    const int NB_E2  = (NE / 2 + 255) / 256;
    const int NB_N   = (NN + 255) / 256;
    const int NB_N16 = (NN * 16 + 255) / 256;

    // fork: GEMM on side stream s2
    cudaEventRecord(evA, 0);
    cudaStreamWaitEvent(s2, evA, 0);
    k_gemm<<<(NN + 255) / 256, 256, 0, s2>>>(x, W);
    cudaEventRecord(evB, s2);

    // CSR build on main stream
    k_zero<<<NB_N, 256>>>();
    k_deg<<<NB_E2, 256>>>(ei);
    k_scan1<<<NBLK_SCAN, SB>>>();
    k_scan3<<<NB_N, 256>>>();
    cudaEventRecord(evD, 0);
    k_fill_d<<<NB_E, 256>>>(ei);

    // src-CSR fill on s3, overlapped with pass1/pass2
    cudaStreamWaitEvent(s3, evD, 0);
    k_fill_s<<<NB_E, 256, 0, s3>>>(ei);
    cudaEventRecord(evC, s3);

    // join GEMM
    cudaStreamWaitEvent(0, evB, 0);
    k_pass1<<<NB_N16, 256>>>(b);
    k_pass2<<<NB_N16, 256>>>();
    k_sum<<<NSUMB, 256>>>(temp);
    k_q<<<NB_N, 256>>>(temp);

    // join src-CSR
    cudaStreamWaitEvent(0, evC, 0);
    k_pass3<<<NB_N16, 256>>>(wgt, out);
}